// round 14
// baseline (speedup 1.0000x reference)
#include <cuda_runtime.h>
#include <cuda_fp16.h>
#include <cuda_bf16.h>

#define BB   8
#define CIN  256
#define HL   64
#define WL   64
#define CMID 64
#define HHI  128
#define WHI  128
#define HP   136   // padded hi-res (pad 4 each side)
#define EPSV 1e-5f

// ------------------------- device scratch -------------------------
__device__ float g_WT[CIN * CMID];              // folded transposed 1x1 weights [k][co]
__device__ float g_bias1[CMID];
__device__ float g_EWr[576 * 112];              // folded enc weights [k][m=q*28+kk] (cout=q+4kk)
__device__ float g_bias2r[112];                 // [q*28+kk]
__device__ float g_W1[BB * CMID * HL * WL];     // conv1 output (8,64,64,64)
__device__ float g_Wsm[BB * HHI * WHI * 25];    // softmaxed weights, [b][y][x][25]
__device__ __half g_Xuh[(size_t)BB * CIN * HP * HP]; // padded bilinear upsample (fp16)
__device__ float g_part[2 * BB * 32 * 112 * 128];    // split-K partials (29.4MB)

// packed fp32x2 FMA (bit-exact 2x fp32 fma)
__device__ __forceinline__ void ffma2(float2& c, float2 a, float2 b) {
    asm("fma.rn.f32x2 %0, %1, %2, %0;"
        : "+l"(reinterpret_cast<unsigned long long&>(c))
        : "l"(reinterpret_cast<unsigned long long&>(a)),
          "l"(reinterpret_cast<unsigned long long&>(b)));
}

// ------------------------- K0: fold BN into weights -------------------------
__global__ void k0_prep(const float* __restrict__ comp_w, const float* __restrict__ comp_b,
                        const float* __restrict__ g1, const float* __restrict__ b1,
                        const float* __restrict__ m1, const float* __restrict__ v1,
                        const float* __restrict__ enc_w, const float* __restrict__ enc_b,
                        const float* __restrict__ g2, const float* __restrict__ b2,
                        const float* __restrict__ m2, const float* __restrict__ v2) {
    int idx = blockIdx.x * 256 + threadIdx.x;
    if (idx < CIN * CMID) {
        int k = idx / CMID, co = idx % CMID;
        float s = g1[co] * rsqrtf(v1[co] + EPSV);
        g_WT[idx] = comp_w[co * CIN + k] * s;
    }
    if (idx < CMID) {
        float s = g1[idx] * rsqrtf(v1[idx] + EPSV);
        g_bias1[idx] = s * (comp_b[idx] - m1[idx]) + b1[idx];
    }
    if (idx < 576 * 112) {
        int k = idx / 112, r = idx % 112;
        int q = r / 28, kk = r % 28;
        float val = 0.f;
        if (kk < 25) {
            int cout = q + 4 * kk;
            float s = g2[cout] * rsqrtf(v2[cout] + EPSV);
            val = enc_w[cout * 576 + k] * s;
        }
        g_EWr[idx] = val;
    }
    if (idx < 112) {
        int q = idx / 28, kk = idx % 28;
        float val = 0.f;
        if (kk < 25) {
            int cout = q + 4 * kk;
            float s = g2[cout] * rsqrtf(v2[cout] + EPSV);
            val = s * (enc_b[cout] - m2[cout]) + b2[cout];
        }
        g_bias2r[idx] = val;
    }
}

// ------------------------- K1: 1x1 conv GEMM + bias + relu (f32x2) ----------------
__global__ __launch_bounds__(256) void k1_conv1(const float* __restrict__ X) {
    __shared__ __align__(16) float Xs[16][128];
    __shared__ __align__(16) float Wts[16][64];
    int tid = threadIdx.x;
    int r = tid >> 5;
    int c = tid & 31;
    int b = blockIdx.y;
    int p0 = blockIdx.x * 128;
    const float* Xb = X + (size_t)b * CIN * HL * WL;

    float2 acc2[4][4];
#pragma unroll
    for (int i = 0; i < 4; i++)
#pragma unroll
        for (int j = 0; j < 4; j++) acc2[i][j] = make_float2(0.f, 0.f);

    for (int k0 = 0; k0 < CIN; k0 += 16) {
        __syncthreads();
#pragma unroll
        for (int i = tid; i < 512; i += 256) {
            int kk = i >> 5, pp = (i & 31) * 4;
            *(float4*)&Xs[kk][pp] = *(const float4*)&Xb[(size_t)(k0 + kk) * (HL * WL) + p0 + pp];
        }
        {
            int kk = tid >> 4, co = (tid & 15) * 4;
            *(float4*)&Wts[kk][co] = *(const float4*)&g_WT[(k0 + kk) * CMID + co];
        }
        __syncthreads();
#pragma unroll
        for (int kk = 0; kk < 16; kk++) {
            float2 w2[4]; float x[4];
            *(float4*)&w2[0] = *(float4*)&Wts[kk][r * 8];
            *(float4*)&w2[2] = *(float4*)&Wts[kk][r * 8 + 4];
            *(float4*)&x[0] = *(float4*)&Xs[kk][c * 4];
            float2 xd[4];
#pragma unroll
            for (int j = 0; j < 4; j++) xd[j] = make_float2(x[j], x[j]);
#pragma unroll
            for (int i = 0; i < 4; i++)
#pragma unroll
                for (int j = 0; j < 4; j++) ffma2(acc2[i][j], w2[i], xd[j]);
        }
    }
#pragma unroll
    for (int i = 0; i < 4; i++) {
        int co0 = r * 8 + 2 * i;
        float b0 = g_bias1[co0], b1 = g_bias1[co0 + 1];
        float4 v0, v1;
        v0.x = fmaxf(acc2[i][0].x + b0, 0.f); v0.y = fmaxf(acc2[i][1].x + b0, 0.f);
        v0.z = fmaxf(acc2[i][2].x + b0, 0.f); v0.w = fmaxf(acc2[i][3].x + b0, 0.f);
        v1.x = fmaxf(acc2[i][0].y + b1, 0.f); v1.y = fmaxf(acc2[i][1].y + b1, 0.f);
        v1.z = fmaxf(acc2[i][2].y + b1, 0.f); v1.w = fmaxf(acc2[i][3].y + b1, 0.f);
        *(float4*)&g_W1[((size_t)b * CMID + co0) * (HL * WL) + p0 + c * 4] = v0;
        *(float4*)&g_W1[((size_t)b * CMID + co0 + 1) * (HL * WL) + p0 + c * 4] = v1;
    }
}

// ------------------------- K2 main: split-K 3x3 conv GEMM, raw partials -----------
// grid (32 tiles, 8 batch, 2 K-halves). 256 thr: mg 7 couts, ng 8 px. 4 cin-chunks.
__global__ __launch_bounds__(256) void k2_main() {
    __shared__ __align__(16) float smem[9664];
    float* tin = smem;
    float* twt = smem + 1600;

    int tid = threadIdx.x;
    int mg = tid >> 4;
    int ng = tid & 15;
    int py = ng >> 1;
    int px0 = (ng & 1) * 8;
    int b = blockIdx.y;
    int kz = blockIdx.z;
    int y0 = (blockIdx.x >> 2) * 8;
    int x0 = (blockIdx.x & 3) * 16;

    int soff[6]; int goff[6]; bool inb[6]; bool val[6];
#pragma unroll
    for (int i = 0; i < 6; i++) {
        int l = tid + i * 256;
        inb[i] = (l < 1440);
        int ls = inb[i] ? l : 0;
        int cin = ls / 180, rem = ls % 180;
        int ty = rem / 18, tx = rem % 18;
        int gy = y0 + ty - 1, gx = x0 + tx - 1;
        val[i] = inb[i] && gy >= 0 && gy < HL && gx >= 0 && gx < WL;
        soff[i] = cin * 200 + ty * 20 + tx;
        goff[i] = (cin * HL + gy) * WL + gx;
    }
    const float* w1base = g_W1 + (size_t)b * CMID * HL * WL;

    float2 acc[7][4];
#pragma unroll
    for (int i = 0; i < 7; i++)
#pragma unroll
        for (int j = 0; j < 4; j++) acc[i][j] = make_float2(0.f, 0.f);

    for (int cc = 0; cc < 4; cc++) {
        int ch = kz * 4 + cc;
        __syncthreads();
        const float* w1c = w1base + ch * 8 * HL * WL;
#pragma unroll
        for (int i = 0; i < 6; i++) {
            float v = val[i] ? __ldg(w1c + goff[i]) : 0.f;
            if (inb[i]) tin[soff[i]] = v;
        }
        {
            const float4* src = (const float4*)(g_EWr + ch * 8064);
            float4* dst = (float4*)twt;
#pragma unroll
            for (int i = 0; i < 7; i++) dst[tid + i * 256] = src[tid + i * 256];
            if (tid < 224) dst[tid + 1792] = src[tid + 1792];
        }
        __syncthreads();
#pragma unroll 2
        for (int cin = 0; cin < 8; cin++)
#pragma unroll
            for (int dy = 0; dy < 3; dy++) {
                const float* rp = &tin[cin * 200 + (py + dy) * 20 + px0];
                float2 pe[5];
#pragma unroll
                for (int k = 0; k < 5; k++) pe[k] = *(const float2*)(rp + 2 * k);
                float2 po[4];
#pragma unroll
                for (int k = 0; k < 4; k++) po[k] = make_float2(pe[k].y, pe[k + 1].x);
#pragma unroll
                for (int dx = 0; dx < 3; dx++) {
                    int kl = cin * 9 + dy * 3 + dx;
                    const float* wp = &twt[kl * 112 + mg * 7];
                    const float2* P = (dx == 0) ? pe : (dx == 1) ? po : (pe + 1);
#pragma unroll
                    for (int i = 0; i < 7; i++) {
                        float w = wp[i];
                        float2 w2 = make_float2(w, w);
#pragma unroll
                        for (int j = 0; j < 4; j++) ffma2(acc[i][j], w2, P[j]);
                    }
                }
            }
    }

    // store raw partials: [kz][b][tile][m=112][px=128]
    float* pbase = g_part + (((size_t)(kz * BB + b) * 32 + blockIdx.x) * 112) * 128;
#pragma unroll
    for (int i = 0; i < 7; i++) {
        float* row = pbase + (mg * 7 + i) * 128 + py * 16 + px0;
#pragma unroll
        for (int j = 0; j < 4; j++) *(float2*)(row + 2 * j) = acc[i][j];
    }
}

// ------------------------- K2 epilogue: sum halves + bias + softmax ---------------
// grid (32 tiles, 8 batch), 512 thr: q = tid>>7, px = tid&127.
__global__ __launch_bounds__(512) void k2_epi() {
    int tid = threadIdx.x;
    int q = tid >> 7;
    int px = tid & 127;
    int b = blockIdx.y;
    int tile = blockIdx.x;
    int y0 = (tile >> 2) * 8;
    int x0 = (tile & 3) * 16;
    int py = px >> 4, pxx = px & 15;

    const float* pA = g_part + (((size_t)(0 * BB + b) * 32 + tile) * 112) * 128 + px;
    const float* pB = g_part + (((size_t)(1 * BB + b) * 32 + tile) * 112) * 128 + px;

    float a[25];
    float mx = -1e30f;
#pragma unroll
    for (int kk = 0; kk < 25; kk++) {
        int m = q * 28 + kk;
        a[kk] = __ldg(pA + m * 128) + __ldg(pB + m * 128) + __ldg(&g_bias2r[m]);
        mx = fmaxf(mx, a[kk]);
    }
    float s = 0.f;
#pragma unroll
    for (int kk = 0; kk < 25; kk++) { a[kk] = __expf(a[kk] - mx); s += a[kk]; }
    float inv = 1.0f / s;
    int Y = 2 * (y0 + py) + (q >> 1);
    int X = 2 * (x0 + pxx) + (q & 1);
    float* dst = &g_Wsm[((size_t)(b * HHI + Y) * WHI + X) * 25];
#pragma unroll
    for (int kk = 0; kk < 25; kk++) dst[kk] = a[kk] * inv;
}

// ------------------------- K_bil: bilinear x2 upsample -> fp16 padded scratch -----
__global__ __launch_bounds__(256) void k_bilinear(const float* __restrict__ X) {
    int gid = blockIdx.x * 256 + threadIdx.x;
    int xg = gid % 17; int t = gid / 17;
    int yp = t % HP;  t /= HP;
    int c = t % CIN;  int b = t / CIN;
    int y = yp - 4;
    float v[8];
#pragma unroll
    for (int u = 0; u < 8; u++) v[u] = 0.f;
    if (y >= 0 && y < HHI) {
        int ry = y & 1, yl = y >> 1;
        int ya, yb; float wya, wyb;
        if (ry == 0) { ya = max(yl - 1, 0); yb = yl; wya = 0.25f; wyb = 0.75f; }
        else         { ya = yl; yb = min(yl + 1, HL - 1); wya = 0.75f; wyb = 0.25f; }
        const float* ra = X + ((size_t)(b * CIN + c) * HL + ya) * WL;
        const float* rb = X + ((size_t)(b * CIN + c) * HL + yb) * WL;
#pragma unroll
        for (int u = 0; u < 8; u++) {
            int x = xg * 8 + u - 4;
            if (x >= 0 && x < WHI) {
                int rx = x & 1, xl = x >> 1;
                int xa, xb; float wxa, wxb;
                if (rx == 0) { xa = max(xl - 1, 0); xb = xl; wxa = 0.25f; wxb = 0.75f; }
                else         { xa = xl; xb = min(xl + 1, WL - 1); wxa = 0.75f; wxb = 0.25f; }
                v[u] = wya * (wxa * __ldg(ra + xa) + wxb * __ldg(ra + xb)) +
                       wyb * (wxa * __ldg(rb + xa) + wxb * __ldg(rb + xb));
            }
        }
    }
    __half2 hv[4];
#pragma unroll
    for (int u = 0; u < 4; u++) hv[u] = __floats2half2_rn(v[2 * u], v[2 * u + 1]);
    *(uint4*)&g_Xuh[(((size_t)(b * CIN + c) * HP) + yp) * HP + xg * 8] = *(uint4*)hv;
}

// ------------------------- K3: reassembly (fp16, lean regs, z=16) -----------------
// block 128 thr: 4 rows x 32 quads, grid (32, 8, 16). thread: 4 x-px, 16 channels.
__global__ __launch_bounds__(128) void k3_reassemble(float* __restrict__ out) {
    int tid = threadIdx.x;
    int y = blockIdx.x * 4 + (tid >> 5);
    int x4 = (tid & 31) * 4;
    int b = blockIdx.y;
    int c0 = blockIdx.z * 16;

    float2 wA[25], wB[25];
    const float* wb = &g_Wsm[((size_t)(b * HHI + y) * WHI + x4) * 25];
#pragma unroll
    for (int k = 0; k < 25; k++) {
        wA[k] = make_float2(__ldg(wb + k),      __ldg(wb + 25 + k));
        wB[k] = make_float2(__ldg(wb + 50 + k), __ldg(wb + 75 + k));
    }

    const __half* xr = &g_Xuh[(((size_t)(b * CIN + c0) * HP) + y) * HP + x4];
    float* ob = out + ((size_t)(b * CIN + c0) * HHI + y) * WHI + x4;
    const size_t chs = (size_t)HP * HP;

#pragma unroll 2
    for (int c = 0; c < 16; c++) {
        const __half* xc = xr + (size_t)c * chs;
        float2 aP0e = make_float2(0.f, 0.f), aP0o = make_float2(0.f, 0.f);
        float2 aP1e = make_float2(0.f, 0.f), aP1o = make_float2(0.f, 0.f);
#pragma unroll
        for (int i = 0; i < 5; i++) {
            const __half* rp = xc + 2 * i * HP;
            uint2 r0 = *(const uint2*)(rp);
            uint2 r1 = *(const uint2*)(rp + 4);
            uint2 r2 = *(const uint2*)(rp + 8);
            float2 pr[6];
            pr[0] = __half22float2(*(const __half2*)&r0.x);
            pr[1] = __half22float2(*(const __half2*)&r0.y);
            pr[2] = __half22float2(*(const __half2*)&r1.x);
            pr[3] = __half22float2(*(const __half2*)&r1.y);
            pr[4] = __half22float2(*(const __half2*)&r2.x);
            pr[5] = __half22float2(*(const __half2*)&r2.y);
            float2& a0 = (i & 1) ? aP0o : aP0e;
            float2& a1 = (i & 1) ? aP1o : aP1e;
#pragma unroll
            for (int j = 0; j < 5; j++) {
                ffma2(a0, wA[i * 5 + j], pr[j]);
                ffma2(a1, wB[i * 5 + j], pr[j + 1]);
            }
        }
        float2 aP0 = make_float2(aP0e.x + aP0o.x, aP0e.y + aP0o.y);
        float2 aP1 = make_float2(aP1e.x + aP1o.x, aP1e.y + aP1o.y);
        *(float4*)(ob + (size_t)c * HHI * WHI) = make_float4(aP0.x, aP0.y, aP1.x, aP1.y);
    }
}

// ------------------------- launch -------------------------
extern "C" void kernel_launch(void* const* d_in, const int* in_sizes, int n_in,
                              void* d_out, int out_size) {
    const float* X      = (const float*)d_in[0];
    const float* comp_w = (const float*)d_in[1];
    const float* comp_b = (const float*)d_in[2];
    const float* bn1_g  = (const float*)d_in[3];
    const float* bn1_b  = (const float*)d_in[4];
    const float* bn1_m  = (const float*)d_in[5];
    const float* bn1_v  = (const float*)d_in[6];
    const float* enc_w  = (const float*)d_in[7];
    const float* enc_b  = (const float*)d_in[8];
    const float* bn2_g  = (const float*)d_in[9];
    const float* bn2_b  = (const float*)d_in[10];
    const float* bn2_m  = (const float*)d_in[11];
    const float* bn2_v  = (const float*)d_in[12];
    float* out = (float*)d_out;

    k0_prep<<<252, 256>>>(comp_w, comp_b, bn1_g, bn1_b, bn1_m, bn1_v,
                          enc_w, enc_b, bn2_g, bn2_b, bn2_m, bn2_v);
    k1_conv1<<<dim3(32, 8), 256>>>(X);
    k_bilinear<<<18496, 256>>>(X);
    k2_main<<<dim3(32, 8, 2), 256>>>();
    k2_epi<<<dim3(32, 8), 512>>>();
    k3_reassemble<<<dim3(32, 8, 16), 128>>>(out);
}

// round 15
// speedup vs baseline: 1.0963x; 1.0963x over previous
#include <cuda_runtime.h>
#include <cuda_fp16.h>
#include <cuda_bf16.h>

#define BB   8
#define CIN  256
#define HL   64
#define WL   64
#define CMID 64
#define HHI  128
#define WHI  128
#define HP   136   // padded hi-res (pad 4 each side)
#define EPSV 1e-5f

// ------------------------- device scratch -------------------------
__device__ float g_WT[CIN * CMID];              // folded transposed 1x1 weights [k][co]
__device__ float g_bias1[CMID];
__device__ float g_EWr[576 * 112];              // folded enc weights [k][m=q*28+kk] (cout=q+4kk)
__device__ float g_bias2r[112];                 // [q*28+kk]
__device__ float g_W1[BB * CMID * HL * WL];     // conv1 output (8,64,64,64)
__device__ float g_Wsm[BB * HHI * WHI * 25];    // softmaxed weights, [b][y][x][25]
__device__ __align__(16) __half g_Xuh[(size_t)BB * CIN * HP * HP]; // padded bilinear upsample (fp16)

// packed fp32x2 FMA (bit-exact 2x fp32 fma)
__device__ __forceinline__ void ffma2(float2& c, float2 a, float2 b) {
    asm("fma.rn.f32x2 %0, %1, %2, %0;"
        : "+l"(reinterpret_cast<unsigned long long&>(c))
        : "l"(reinterpret_cast<unsigned long long&>(a)),
          "l"(reinterpret_cast<unsigned long long&>(b)));
}

// ------------------------- K0: fold BN into weights -------------------------
__global__ void k0_prep(const float* __restrict__ comp_w, const float* __restrict__ comp_b,
                        const float* __restrict__ g1, const float* __restrict__ b1,
                        const float* __restrict__ m1, const float* __restrict__ v1,
                        const float* __restrict__ enc_w, const float* __restrict__ enc_b,
                        const float* __restrict__ g2, const float* __restrict__ b2,
                        const float* __restrict__ m2, const float* __restrict__ v2) {
    int idx = blockIdx.x * 256 + threadIdx.x;
    if (idx < CIN * CMID) {
        int k = idx / CMID, co = idx % CMID;
        float s = g1[co] * rsqrtf(v1[co] + EPSV);
        g_WT[idx] = comp_w[co * CIN + k] * s;
    }
    if (idx < CMID) {
        float s = g1[idx] * rsqrtf(v1[idx] + EPSV);
        g_bias1[idx] = s * (comp_b[idx] - m1[idx]) + b1[idx];
    }
    if (idx < 576 * 112) {
        int k = idx / 112, r = idx % 112;
        int q = r / 28, kk = r % 28;
        float val = 0.f;
        if (kk < 25) {
            int cout = q + 4 * kk;
            float s = g2[cout] * rsqrtf(v2[cout] + EPSV);
            val = enc_w[cout * 576 + k] * s;
        }
        g_EWr[idx] = val;
    }
    if (idx < 112) {
        int q = idx / 28, kk = idx % 28;
        float val = 0.f;
        if (kk < 25) {
            int cout = q + 4 * kk;
            float s = g2[cout] * rsqrtf(v2[cout] + EPSV);
            val = s * (enc_b[cout] - m2[cout]) + b2[cout];
        }
        g_bias2r[idx] = val;
    }
}

// ------------------------- K1: 1x1 conv GEMM + bias + relu (f32x2) ----------------
__global__ __launch_bounds__(256) void k1_conv1(const float* __restrict__ X) {
    __shared__ __align__(16) float Xs[16][128];
    __shared__ __align__(16) float Wts[16][64];
    int tid = threadIdx.x;
    int r = tid >> 5;
    int c = tid & 31;
    int b = blockIdx.y;
    int p0 = blockIdx.x * 128;
    const float* Xb = X + (size_t)b * CIN * HL * WL;

    float2 acc2[4][4];
#pragma unroll
    for (int i = 0; i < 4; i++)
#pragma unroll
        for (int j = 0; j < 4; j++) acc2[i][j] = make_float2(0.f, 0.f);

    for (int k0 = 0; k0 < CIN; k0 += 16) {
        __syncthreads();
#pragma unroll
        for (int i = tid; i < 512; i += 256) {
            int kk = i >> 5, pp = (i & 31) * 4;
            *(float4*)&Xs[kk][pp] = *(const float4*)&Xb[(size_t)(k0 + kk) * (HL * WL) + p0 + pp];
        }
        {
            int kk = tid >> 4, co = (tid & 15) * 4;
            *(float4*)&Wts[kk][co] = *(const float4*)&g_WT[(k0 + kk) * CMID + co];
        }
        __syncthreads();
#pragma unroll
        for (int kk = 0; kk < 16; kk++) {
            float2 w2[4]; float x[4];
            *(float4*)&w2[0] = *(float4*)&Wts[kk][r * 8];
            *(float4*)&w2[2] = *(float4*)&Wts[kk][r * 8 + 4];
            *(float4*)&x[0] = *(float4*)&Xs[kk][c * 4];
            float2 xd[4];
#pragma unroll
            for (int j = 0; j < 4; j++) xd[j] = make_float2(x[j], x[j]);
#pragma unroll
            for (int i = 0; i < 4; i++)
#pragma unroll
                for (int j = 0; j < 4; j++) ffma2(acc2[i][j], w2[i], xd[j]);
        }
    }
#pragma unroll
    for (int i = 0; i < 4; i++) {
        int co0 = r * 8 + 2 * i;
        float b0 = g_bias1[co0], b1 = g_bias1[co0 + 1];
        float4 v0, v1;
        v0.x = fmaxf(acc2[i][0].x + b0, 0.f); v0.y = fmaxf(acc2[i][1].x + b0, 0.f);
        v0.z = fmaxf(acc2[i][2].x + b0, 0.f); v0.w = fmaxf(acc2[i][3].x + b0, 0.f);
        v1.x = fmaxf(acc2[i][0].y + b1, 0.f); v1.y = fmaxf(acc2[i][1].y + b1, 0.f);
        v1.z = fmaxf(acc2[i][2].y + b1, 0.f); v1.w = fmaxf(acc2[i][3].y + b1, 0.f);
        *(float4*)&g_W1[((size_t)b * CMID + co0) * (HL * WL) + p0 + c * 4] = v0;
        *(float4*)&g_W1[((size_t)b * CMID + co0 + 1) * (HL * WL) + p0 + c * 4] = v1;
    }
}

// ------------------------- K2: 3x3 conv GEMM + softmax epilogue (fused, R12) ------
__global__ __launch_bounds__(256, 2) void k2_kernelpred() {
    __shared__ __align__(16) float smem[9664];
    float* tin = smem;
    float* twt = smem + 1600;

    int tid = threadIdx.x;
    int mg = tid >> 4;
    int ng = tid & 15;
    int py = ng >> 1;
    int px0 = (ng & 1) * 8;
    int b = blockIdx.y;
    int y0 = (blockIdx.x >> 2) * 8;
    int x0 = (blockIdx.x & 3) * 16;

    int soff[6]; int goff[6]; bool inb[6]; bool val[6];
#pragma unroll
    for (int i = 0; i < 6; i++) {
        int l = tid + i * 256;
        inb[i] = (l < 1440);
        int ls = inb[i] ? l : 0;
        int cin = ls / 180, rem = ls % 180;
        int ty = rem / 18, tx = rem % 18;
        int gy = y0 + ty - 1, gx = x0 + tx - 1;
        val[i] = inb[i] && gy >= 0 && gy < HL && gx >= 0 && gx < WL;
        soff[i] = cin * 200 + ty * 20 + tx;
        goff[i] = (cin * HL + gy) * WL + gx;
    }
    const float* w1base = g_W1 + (size_t)b * CMID * HL * WL;

    float2 acc[7][4];
#pragma unroll
    for (int i = 0; i < 7; i++)
#pragma unroll
        for (int j = 0; j < 4; j++) acc[i][j] = make_float2(0.f, 0.f);

    for (int ch = 0; ch < 8; ch++) {
        __syncthreads();
        const float* w1c = w1base + ch * 8 * HL * WL;
#pragma unroll
        for (int i = 0; i < 6; i++) {
            float v = val[i] ? __ldg(w1c + goff[i]) : 0.f;
            if (inb[i]) tin[soff[i]] = v;
        }
        {
            const float4* src = (const float4*)(g_EWr + ch * 8064);
            float4* dst = (float4*)twt;
#pragma unroll
            for (int i = 0; i < 7; i++) dst[tid + i * 256] = src[tid + i * 256];
            if (tid < 224) dst[tid + 1792] = src[tid + 1792];
        }
        __syncthreads();
#pragma unroll 2
        for (int cin = 0; cin < 8; cin++)
#pragma unroll
            for (int dy = 0; dy < 3; dy++) {
                const float* rp = &tin[cin * 200 + (py + dy) * 20 + px0];
                float2 pe[5];
#pragma unroll
                for (int k = 0; k < 5; k++) pe[k] = *(const float2*)(rp + 2 * k);
                float2 po[4];
#pragma unroll
                for (int k = 0; k < 4; k++) po[k] = make_float2(pe[k].y, pe[k + 1].x);
#pragma unroll
                for (int dx = 0; dx < 3; dx++) {
                    int kl = cin * 9 + dy * 3 + dx;
                    const float* wp = &twt[kl * 112 + mg * 7];
                    const float2* P = (dx == 0) ? pe : (dx == 1) ? po : (pe + 1);
#pragma unroll
                    for (int i = 0; i < 7; i++) {
                        float w = wp[i];
                        float2 w2 = make_float2(w, w);
#pragma unroll
                        for (int j = 0; j < 4; j++) ffma2(acc[i][j], w2, P[j]);
                    }
                }
            }
    }

    float* sL = smem;                                     // [112][66]
    for (int half = 0; half < 2; half++) {
        __syncthreads();
        if ((ng & 1) == half) {
            int colb = py * 8;
#pragma unroll
            for (int i = 0; i < 7; i++) {
                float* row = &sL[(mg * 7 + i) * 66 + colb];
#pragma unroll
                for (int j = 0; j < 4; j++) {
                    row[2 * j] = acc[i][j].x;
                    row[2 * j + 1] = acc[i][j].y;
                }
            }
        }
        __syncthreads();
        {
            int q = tid >> 6;
            int pp = tid & 63;
            int pyy = pp >> 3, pxx = pp & 7;
            int yl = y0 + pyy, xl = x0 + half * 8 + pxx;
            float a[25];
            float mx = -1e30f;
#pragma unroll
            for (int kk = 0; kk < 25; kk++) {
                a[kk] = sL[(q * 28 + kk) * 66 + pp] + __ldg(&g_bias2r[q * 28 + kk]);
                mx = fmaxf(mx, a[kk]);
            }
            float s = 0.f;
#pragma unroll
            for (int kk = 0; kk < 25; kk++) { a[kk] = __expf(a[kk] - mx); s += a[kk]; }
            float inv = 1.0f / s;
            int Y = 2 * yl + (q >> 1), X = 2 * xl + (q & 1);
            float* dst = &g_Wsm[((size_t)(b * HHI + Y) * WHI + X) * 25];
#pragma unroll
            for (int kk = 0; kk < 25; kk++) dst[kk] = a[kk] * inv;
        }
    }
}

// ------------------------- K_bil: bilinear x2 upsample -> fp16 padded scratch -----
__global__ __launch_bounds__(256) void k_bilinear(const float* __restrict__ X) {
    int gid = blockIdx.x * 256 + threadIdx.x;
    int xg = gid % 17; int t = gid / 17;
    int yp = t % HP;  t /= HP;
    int c = t % CIN;  int b = t / CIN;
    int y = yp - 4;
    float v[8];
#pragma unroll
    for (int u = 0; u < 8; u++) v[u] = 0.f;
    if (y >= 0 && y < HHI) {
        int ry = y & 1, yl = y >> 1;
        int ya, yb; float wya, wyb;
        if (ry == 0) { ya = max(yl - 1, 0); yb = yl; wya = 0.25f; wyb = 0.75f; }
        else         { ya = yl; yb = min(yl + 1, HL - 1); wya = 0.75f; wyb = 0.25f; }
        const float* ra = X + ((size_t)(b * CIN + c) * HL + ya) * WL;
        const float* rb = X + ((size_t)(b * CIN + c) * HL + yb) * WL;
#pragma unroll
        for (int u = 0; u < 8; u++) {
            int x = xg * 8 + u - 4;
            if (x >= 0 && x < WHI) {
                int rx = x & 1, xl = x >> 1;
                int xa, xb; float wxa, wxb;
                if (rx == 0) { xa = max(xl - 1, 0); xb = xl; wxa = 0.25f; wxb = 0.75f; }
                else         { xa = xl; xb = min(xl + 1, WL - 1); wxa = 0.75f; wxb = 0.25f; }
                v[u] = wya * (wxa * __ldg(ra + xa) + wxb * __ldg(ra + xb)) +
                       wyb * (wxa * __ldg(rb + xa) + wxb * __ldg(rb + xb));
            }
        }
    }
    __half2 hv[4];
#pragma unroll
    for (int u = 0; u < 4; u++) hv[u] = __floats2half2_rn(v[2 * u], v[2 * u + 1]);
    *(uint4*)&g_Xuh[(((size_t)(b * CIN + c) * HP) + yp) * HP + xg * 8] = *(uint4*)hv;
}

// ------------------------- K3: reassembly, warp-synchronous smem staging ----------
// block 128 thr (4 warps), grid (32, 8, 8). Warp = one output row, 128 x (4 px/lane),
// 32 channels. Per channel: warp stages its 5 tap rows (5x136 halfs) for c+1 via 3
// coalesced LDG.128/lane into a private double-buffered smem slab; computes channel c
// from smem (short-latency LDS). Only __syncwarp — no block barriers.
__global__ __launch_bounds__(128) void k3_reassemble(float* __restrict__ out) {
    __shared__ __align__(16) __half sbuf[4][2][5 * 144];   // 11520 B
    int tid = threadIdx.x;
    int wid = tid >> 5;
    int lane = tid & 31;
    int y = blockIdx.x * 4 + wid;
    int x4 = lane * 4;
    int b = blockIdx.y;
    int c0 = blockIdx.z * 32;

    float2 wA[25], wB[25];
    {
        const float* wb = &g_Wsm[((size_t)(b * HHI + y) * WHI + x4) * 25];
#pragma unroll
        for (int k = 0; k < 25; k++) {
            wA[k] = make_float2(__ldg(wb + k),      __ldg(wb + 25 + k));
            wB[k] = make_float2(__ldg(wb + 50 + k), __ldg(wb + 75 + k));
        }
    }

    // staging slots: 85 uint4 (5 rows x 17); lane handles s = lane, lane+32, lane+64
    int soff[3], dstoff[3];
#pragma unroll
    for (int i = 0; i < 3; i++) {
        int s = lane + 32 * i;
        int ss = (s < 85) ? s : 0;
        int r = ss / 17, c16 = ss % 17;
        soff[i]   = (2 * r) * HP + c16 * 8;    // halfs, within channel at padded row y
        dstoff[i] = r * 144 + c16 * 8;         // halfs, within smem slab
    }
    bool sv2 = (lane + 64) < 85;

    const __half* xrow = &g_Xuh[(((size_t)(b * CIN + c0) * HP) + y) * HP];
    const size_t chs = (size_t)HP * HP;
    float* ob = out + ((size_t)(b * CIN + c0) * HHI + y) * WHI + x4;

    uint4 st0, st1, st2;
    // prologue: stage channel 0 into buf 0
    st0 = __ldg((const uint4*)(xrow + soff[0]));
    st1 = __ldg((const uint4*)(xrow + soff[1]));
    if (sv2) st2 = __ldg((const uint4*)(xrow + soff[2]));
    *(uint4*)&sbuf[wid][0][dstoff[0]] = st0;
    *(uint4*)&sbuf[wid][0][dstoff[1]] = st1;
    if (sv2) *(uint4*)&sbuf[wid][0][dstoff[2]] = st2;

    int buf = 0;
    for (int c = 0; c < 32; c++) {
        // prefetch next channel's rows (independent, long latency)
        if (c + 1 < 32) {
            const __half* xn = xrow + (size_t)(c + 1) * chs;
            st0 = __ldg((const uint4*)(xn + soff[0]));
            st1 = __ldg((const uint4*)(xn + soff[1]));
            if (sv2) st2 = __ldg((const uint4*)(xn + soff[2]));
        }
        __syncwarp();                         // staged data for channel c visible
        const __half* vb = &sbuf[wid][buf][0];
        float2 aP0e = make_float2(0.f, 0.f), aP0o = make_float2(0.f, 0.f);
        float2 aP1e = make_float2(0.f, 0.f), aP1o = make_float2(0.f, 0.f);
#pragma unroll
        for (int i = 0; i < 5; i++) {
            const __half* rp = vb + i * 144 + x4;
            uint2 r0 = *(const uint2*)(rp);
            uint2 r1 = *(const uint2*)(rp + 4);
            uint2 r2 = *(const uint2*)(rp + 8);
            float2 pr[6];
            pr[0] = __half22float2(*(const __half2*)&r0.x);
            pr[1] = __half22float2(*(const __half2*)&r0.y);
            pr[2] = __half22float2(*(const __half2*)&r1.x);
            pr[3] = __half22float2(*(const __half2*)&r1.y);
            pr[4] = __half22float2(*(const __half2*)&r2.x);
            pr[5] = __half22float2(*(const __half2*)&r2.y);
            float2& a0 = (i & 1) ? aP0o : aP0e;
            float2& a1 = (i & 1) ? aP1o : aP1e;
#pragma unroll
            for (int j = 0; j < 5; j++) {
                ffma2(a0, wA[i * 5 + j], pr[j]);
                ffma2(a1, wB[i * 5 + j], pr[j + 1]);
            }
        }
        float2 aP0 = make_float2(aP0e.x + aP0o.x, aP0e.y + aP0o.y);
        float2 aP1 = make_float2(aP1e.x + aP1o.x, aP1e.y + aP1o.y);
        *(float4*)(ob + (size_t)c * HHI * WHI) = make_float4(aP0.x, aP0.y, aP1.x, aP1.y);
        // store staged channel c+1 into the other buffer
        if (c + 1 < 32) {
            __half* db = &sbuf[wid][buf ^ 1][0];
            *(uint4*)(db + dstoff[0]) = st0;
            *(uint4*)(db + dstoff[1]) = st1;
            if (sv2) *(uint4*)(db + dstoff[2]) = st2;
        }
        buf ^= 1;
    }
}

// ------------------------- launch -------------------------
extern "C" void kernel_launch(void* const* d_in, const int* in_sizes, int n_in,
                              void* d_out, int out_size) {
    const float* X      = (const float*)d_in[0];
    const float* comp_w = (const float*)d_in[1];
    const float* comp_b = (const float*)d_in[2];
    const float* bn1_g  = (const float*)d_in[3];
    const float* bn1_b  = (const float*)d_in[4];
    const float* bn1_m  = (const float*)d_in[5];
    const float* bn1_v  = (const float*)d_in[6];
    const float* enc_w  = (const float*)d_in[7];
    const float* enc_b  = (const float*)d_in[8];
    const float* bn2_g  = (const float*)d_in[9];
    const float* bn2_b  = (const float*)d_in[10];
    const float* bn2_m  = (const float*)d_in[11];
    const float* bn2_v  = (const float*)d_in[12];
    float* out = (float*)d_out;

    k0_prep<<<252, 256>>>(comp_w, comp_b, bn1_g, bn1_b, bn1_m, bn1_v,
                          enc_w, enc_b, bn2_g, bn2_b, bn2_m, bn2_v);
    k1_conv1<<<dim3(32, 8), 256>>>(X);
    k_bilinear<<<18496, 256>>>(X);
    k2_kernelpred<<<dim3(32, 8), 256>>>();
    k3_reassemble<<<dim3(32, 8, 8), 128>>>(out);
}

// round 16
// speedup vs baseline: 1.5038x; 1.3717x over previous
#include <cuda_runtime.h>
#include <cuda_fp16.h>
#include <cuda_bf16.h>

#define BB   8
#define CIN  256
#define HL   64
#define WL   64
#define CMID 64
#define HHI  128
#define WHI  128
#define HP   136   // padded hi-res (pad 4 each side)
#define EPSV 1e-5f

// ------------------------- device scratch -------------------------
__device__ float g_WT[CIN * CMID];              // folded transposed 1x1 weights [k][co]
__device__ float g_bias1[CMID];
__device__ __align__(16) __half g_EWh[36 * 112 * 16]; // folded enc weights fp16 [ks][m][kk]
__device__ float g_bias2r[112];                 // [q*28+kk]
__device__ float g_W1[BB * CMID * HL * WL];     // conv1 output (8,64,64,64)
__device__ float g_Wsm[BB * HHI * WHI * 25];    // softmaxed weights, [b][y][x][25]
__device__ __align__(16) __half g_Xuh[(size_t)BB * CIN * HP * HP]; // bilinear upsample (fp16)

// packed fp32x2 FMA (bit-exact 2x fp32 fma)
__device__ __forceinline__ void ffma2(float2& c, float2 a, float2 b) {
    asm("fma.rn.f32x2 %0, %1, %2, %0;"
        : "+l"(reinterpret_cast<unsigned long long&>(c))
        : "l"(reinterpret_cast<unsigned long long&>(a)),
          "l"(reinterpret_cast<unsigned long long&>(b)));
}

__device__ __forceinline__ void mma16816(float* d, const unsigned* a, unsigned b0, unsigned b1) {
    asm volatile("mma.sync.aligned.m16n8k16.row.col.f32.f16.f16.f32 "
        "{%0,%1,%2,%3}, {%4,%5,%6,%7}, {%8,%9}, {%0,%1,%2,%3};"
        : "+f"(d[0]), "+f"(d[1]), "+f"(d[2]), "+f"(d[3])
        : "r"(a[0]), "r"(a[1]), "r"(a[2]), "r"(a[3]), "r"(b0), "r"(b1));
}

// ------------------------- K0: fold BN into weights -------------------------
__global__ void k0_prep(const float* __restrict__ comp_w, const float* __restrict__ comp_b,
                        const float* __restrict__ g1, const float* __restrict__ b1,
                        const float* __restrict__ m1, const float* __restrict__ v1,
                        const float* __restrict__ enc_w, const float* __restrict__ enc_b,
                        const float* __restrict__ g2, const float* __restrict__ b2,
                        const float* __restrict__ m2, const float* __restrict__ v2) {
    int idx = blockIdx.x * 256 + threadIdx.x;
    if (idx < CIN * CMID) {
        int k = idx / CMID, co = idx % CMID;
        float s = g1[co] * rsqrtf(v1[co] + EPSV);
        g_WT[idx] = comp_w[co * CIN + k] * s;
    }
    if (idx < CMID) {
        float s = g1[idx] * rsqrtf(v1[idx] + EPSV);
        g_bias1[idx] = s * (comp_b[idx] - m1[idx]) + b1[idx];
    }
    if (idx < 36 * 112 * 16) {                   // fp16 enc weights [ks][m][kk]
        int ks = idx / 1792, rem = idx % 1792;
        int m = rem / 16, kk = rem % 16;
        int gk = ks * 16 + kk;
        int q = m / 28, kkk = m % 28;
        float val = 0.f;
        if (kkk < 25) {
            int cout = q + 4 * kkk;
            float s = g2[cout] * rsqrtf(v2[cout] + EPSV);
            val = enc_w[cout * 576 + gk] * s;
        }
        g_EWh[idx] = __float2half(val);
    }
    if (idx < 112) {
        int q = idx / 28, kk = idx % 28;
        float val = 0.f;
        if (kk < 25) {
            int cout = q + 4 * kk;
            float s = g2[cout] * rsqrtf(v2[cout] + EPSV);
            val = s * (enc_b[cout] - m2[cout]) + b2[cout];
        }
        g_bias2r[idx] = val;
    }
}

// ------------------------- K1: 1x1 conv GEMM + bias + relu (f32x2) ----------------
__global__ __launch_bounds__(256) void k1_conv1(const float* __restrict__ X) {
    __shared__ __align__(16) float Xs[16][128];
    __shared__ __align__(16) float Wts[16][64];
    int tid = threadIdx.x;
    int r = tid >> 5;
    int c = tid & 31;
    int b = blockIdx.y;
    int p0 = blockIdx.x * 128;
    const float* Xb = X + (size_t)b * CIN * HL * WL;

    float2 acc2[4][4];
#pragma unroll
    for (int i = 0; i < 4; i++)
#pragma unroll
        for (int j = 0; j < 4; j++) acc2[i][j] = make_float2(0.f, 0.f);

    for (int k0 = 0; k0 < CIN; k0 += 16) {
        __syncthreads();
#pragma unroll
        for (int i = tid; i < 512; i += 256) {
            int kk = i >> 5, pp = (i & 31) * 4;
            *(float4*)&Xs[kk][pp] = *(const float4*)&Xb[(size_t)(k0 + kk) * (HL * WL) + p0 + pp];
        }
        {
            int kk = tid >> 4, co = (tid & 15) * 4;
            *(float4*)&Wts[kk][co] = *(const float4*)&g_WT[(k0 + kk) * CMID + co];
        }
        __syncthreads();
#pragma unroll
        for (int kk = 0; kk < 16; kk++) {
            float2 w2[4]; float x[4];
            *(float4*)&w2[0] = *(float4*)&Wts[kk][r * 8];
            *(float4*)&w2[2] = *(float4*)&Wts[kk][r * 8 + 4];
            *(float4*)&x[0] = *(float4*)&Xs[kk][c * 4];
            float2 xd[4];
#pragma unroll
            for (int j = 0; j < 4; j++) xd[j] = make_float2(x[j], x[j]);
#pragma unroll
            for (int i = 0; i < 4; i++)
#pragma unroll
                for (int j = 0; j < 4; j++) ffma2(acc2[i][j], w2[i], xd[j]);
        }
    }
#pragma unroll
    for (int i = 0; i < 4; i++) {
        int co0 = r * 8 + 2 * i;
        float b0 = g_bias1[co0], b1 = g_bias1[co0 + 1];
        float4 v0, v1;
        v0.x = fmaxf(acc2[i][0].x + b0, 0.f); v0.y = fmaxf(acc2[i][1].x + b0, 0.f);
        v0.z = fmaxf(acc2[i][2].x + b0, 0.f); v0.w = fmaxf(acc2[i][3].x + b0, 0.f);
        v1.x = fmaxf(acc2[i][0].y + b1, 0.f); v1.y = fmaxf(acc2[i][1].y + b1, 0.f);
        v1.z = fmaxf(acc2[i][2].y + b1, 0.f); v1.w = fmaxf(acc2[i][3].y + b1, 0.f);
        *(float4*)&g_W1[((size_t)b * CMID + co0) * (HL * WL) + p0 + c * 4] = v0;
        *(float4*)&g_W1[((size_t)b * CMID + co0 + 1) * (HL * WL) + p0 + c * 4] = v1;
    }
}

// ------------------------- K2: tensor-core 3x3 conv + softmax ---------------------
// GEMM M=112 x N=128px x K=576 via mma.sync m16n8k16 fp16->fp32.
// 256 thr: warps 0..6 = 16 m-rows each; all threads build B panels + softmax.
__global__ __launch_bounds__(256) void k2_tensor() {
    __shared__ __align__(16) char smraw[30720];
    __half* tin = (__half*)smraw;               // [64][10][20] fp16 input tile
    __half* Bs  = (__half*)(smraw + 25600);     // [128][20] fp16 B panel
    float*  sL  = (float*)smraw;                // [112][66] epilogue (reuses tin/Bs)

    int tid = threadIdx.x;
    int wid = tid >> 5, lane = tid & 31;
    int b = blockIdx.y;
    int y0 = (blockIdx.x >> 2) * 8;
    int x0 = (blockIdx.x & 3) * 16;

    // ---- stage input tile 64x10x18 (zero-padded) as fp16 ----
    const float* w1base = g_W1 + (size_t)b * CMID * HL * WL;
    for (int l = tid; l < 11520; l += 256) {
        int cin = l / 180, rem = l % 180;
        int ty = rem / 18, tx = rem % 18;
        int gy = y0 + ty - 1, gx = x0 + tx - 1;
        float v = 0.f;
        if (gy >= 0 && gy < HL && gx >= 0 && gx < WL)
            v = __ldg(w1base + (cin * HL + gy) * WL + gx);
        tin[(cin * 10 + ty) * 20 + tx] = __float2half(v);
    }

    // B-build mapping: thread -> (kk, 8 consecutive n in one py-row)
    int kk = tid & 15;
    int u = tid >> 4;
    int bpy = u >> 1;
    int pxb = (u & 1) * 8;

    // mma mapping
    int r = lane >> 2;
    int c0 = (lane & 3) * 2;
    bool mwarp = (wid < 7);
    int mbase = wid * 16;

    float d[16][4];
#pragma unroll
    for (int f = 0; f < 16; f++)
#pragma unroll
        for (int i = 0; i < 4; i++) d[f][i] = 0.f;

    unsigned aN[4] = {0, 0, 0, 0}, aC[4];
    if (mwarp) {
        const __half* ap = g_EWh + (size_t)(0 * 112 + mbase) * 16;
        aN[0] = *(const unsigned*)(ap + r * 16 + c0);
        aN[1] = *(const unsigned*)(ap + (r + 8) * 16 + c0);
        aN[2] = *(const unsigned*)(ap + r * 16 + c0 + 8);
        aN[3] = *(const unsigned*)(ap + (r + 8) * 16 + c0 + 8);
    }
    __syncthreads();                              // tin ready

    for (int ks = 0; ks < 36; ks++) {
        // ---- build B panel [128 n][16 k] for this k-step ----
        {
            int gk = ks * 16 + kk;
            int cin = gk / 9, r9 = gk % 9;
            int dy = r9 / 3, dx = r9 % 3;
            const __half* tp = tin + (cin * 10 + bpy + dy) * 20 + pxb + dx;
#pragma unroll
            for (int j = 0; j < 8; j++)
                Bs[(u * 8 + j) * 20 + kk] = tp[j];
        }
#pragma unroll
        for (int i = 0; i < 4; i++) aC[i] = aN[i];
        if (mwarp && ks + 1 < 36) {               // prefetch next A fragment
            const __half* ap = g_EWh + (size_t)((ks + 1) * 112 + mbase) * 16;
            aN[0] = *(const unsigned*)(ap + r * 16 + c0);
            aN[1] = *(const unsigned*)(ap + (r + 8) * 16 + c0);
            aN[2] = *(const unsigned*)(ap + r * 16 + c0 + 8);
            aN[3] = *(const unsigned*)(ap + (r + 8) * 16 + c0 + 8);
        }
        __syncthreads();                          // Bs ready
        if (mwarp) {
#pragma unroll
            for (int f = 0; f < 16; f++) {
                int col = f * 8 + r;
                unsigned b0 = *(const unsigned*)(Bs + col * 20 + c0);
                unsigned b1 = *(const unsigned*)(Bs + col * 20 + c0 + 8);
                mma16816(d[f], aC, b0, b1);
            }
        }
        __syncthreads();                          // mma done before Bs overwrite
    }

    // ---- epilogue: transpose via sL (two y-halves), bias + pixel-shuffle softmax --
    for (int half = 0; half < 2; half++) {
        __syncthreads();
        if (mwarp) {
#pragma unroll
            for (int fi = 0; fi < 8; fi++) {
                int f = half * 8 + fi;
                int nn = fi * 8 + c0;
                sL[(mbase + r) * 66 + nn]          = d[f][0];
                sL[(mbase + r) * 66 + nn + 1]      = d[f][1];
                sL[(mbase + r + 8) * 66 + nn]      = d[f][2];
                sL[(mbase + r + 8) * 66 + nn + 1]  = d[f][3];
            }
        }
        __syncthreads();
        {
            int q = tid >> 6;
            int pp = tid & 63;
            int yl = y0 + half * 4 + (pp >> 4);
            int xl = x0 + (pp & 15);
            float a[25];
            float mx = -1e30f;
#pragma unroll
            for (int t = 0; t < 25; t++) {
                a[t] = sL[(q * 28 + t) * 66 + pp] + __ldg(&g_bias2r[q * 28 + t]);
                mx = fmaxf(mx, a[t]);
            }
            float s = 0.f;
#pragma unroll
            for (int t = 0; t < 25; t++) { a[t] = __expf(a[t] - mx); s += a[t]; }
            float inv = 1.0f / s;
            int Y = 2 * yl + (q >> 1), X = 2 * xl + (q & 1);
            float* dst = &g_Wsm[((size_t)(b * HHI + Y) * WHI + X) * 25];
#pragma unroll
            for (int t = 0; t < 25; t++) dst[t] = a[t] * inv;
        }
    }
}

// ------------------------- K_bil: bilinear x2 upsample -> fp16 padded scratch -----
__global__ __launch_bounds__(256) void k_bilinear(const float* __restrict__ X) {
    int gid = blockIdx.x * 256 + threadIdx.x;
    int xg = gid % 17; int t = gid / 17;
    int yp = t % HP;  t /= HP;
    int c = t % CIN;  int b = t / CIN;
    int y = yp - 4;
    float v[8];
#pragma unroll
    for (int u = 0; u < 8; u++) v[u] = 0.f;
    if (y >= 0 && y < HHI) {
        int ry = y & 1, yl = y >> 1;
        int ya, yb; float wya, wyb;
        if (ry == 0) { ya = max(yl - 1, 0); yb = yl; wya = 0.25f; wyb = 0.75f; }
        else         { ya = yl; yb = min(yl + 1, HL - 1); wya = 0.75f; wyb = 0.25f; }
        const float* ra = X + ((size_t)(b * CIN + c) * HL + ya) * WL;
        const float* rb = X + ((size_t)(b * CIN + c) * HL + yb) * WL;
#pragma unroll
        for (int u = 0; u < 8; u++) {
            int x = xg * 8 + u - 4;
            if (x >= 0 && x < WHI) {
                int rx = x & 1, xl = x >> 1;
                int xa, xb; float wxa, wxb;
                if (rx == 0) { xa = max(xl - 1, 0); xb = xl; wxa = 0.25f; wxb = 0.75f; }
                else         { xa = xl; xb = min(xl + 1, WL - 1); wxa = 0.75f; wxb = 0.25f; }
                v[u] = wya * (wxa * __ldg(ra + xa) + wxb * __ldg(ra + xb)) +
                       wyb * (wxa * __ldg(rb + xa) + wxb * __ldg(rb + xb));
            }
        }
    }
    __half2 hv[4];
#pragma unroll
    for (int u = 0; u < 4; u++) hv[u] = __floats2half2_rn(v[2 * u], v[2 * u + 1]);
    *(uint4*)&g_Xuh[(((size_t)(b * CIN + c) * HP) + yp) * HP + xg * 8] = *(uint4*)hv;
}

// ------------------------- K3: reassembly (fp16 loads, 4 fma chains, prefetch) ----
// block 128 thr: 4 rows x 32 quads, grid (32, 8, 8). thread: 4 x-px, 32 channels.
__global__ __launch_bounds__(128) void k3_reassemble(float* __restrict__ out) {
    int tid = threadIdx.x;
    int y = blockIdx.x * 4 + (tid >> 5);
    int x4 = (tid & 31) * 4;
    int b = blockIdx.y;
    int c0 = blockIdx.z * 32;

    float2 wA[25], wB[25];
    const float* wb = &g_Wsm[((size_t)(b * HHI + y) * WHI + x4) * 25];
#pragma unroll
    for (int k = 0; k < 25; k++) {
        wA[k] = make_float2(__ldg(wb + k),      __ldg(wb + 25 + k));
        wB[k] = make_float2(__ldg(wb + 50 + k), __ldg(wb + 75 + k));
    }

    const __half* xr = &g_Xuh[(((size_t)(b * CIN + c0) * HP) + y) * HP + x4];
    float* ob = out + ((size_t)(b * CIN + c0) * HHI + y) * WHI + x4;
    const size_t chs = (size_t)HP * HP;

    uint2 cur[15], nxt[15];
#pragma unroll
    for (int i = 0; i < 5; i++) {
        const __half* rp = xr + 2 * i * HP;
        cur[3 * i]     = *(const uint2*)(rp);
        cur[3 * i + 1] = *(const uint2*)(rp + 4);
        cur[3 * i + 2] = *(const uint2*)(rp + 8);
    }

#pragma unroll 2
    for (int c = 0; c < 32; c++) {
        const __half* xn = xr + (c < 31 ? chs : 0);
#pragma unroll
        for (int i = 0; i < 5; i++) {
            const __half* rp = xn + 2 * i * HP;
            nxt[3 * i]     = *(const uint2*)(rp);
            nxt[3 * i + 1] = *(const uint2*)(rp + 4);
            nxt[3 * i + 2] = *(const uint2*)(rp + 8);
        }
        float2 aP0e = make_float2(0.f, 0.f), aP0o = make_float2(0.f, 0.f);
        float2 aP1e = make_float2(0.f, 0.f), aP1o = make_float2(0.f, 0.f);
#pragma unroll
        for (int i = 0; i < 5; i++) {
            float2 pr[6];
#pragma unroll
            for (int qq = 0; qq < 3; qq++) {
                uint2 rw = cur[3 * i + qq];
                pr[2 * qq]     = __half22float2(*(const __half2*)&rw.x);
                pr[2 * qq + 1] = __half22float2(*(const __half2*)&rw.y);
            }
            float2& a0 = (i & 1) ? aP0o : aP0e;
            float2& a1 = (i & 1) ? aP1o : aP1e;
#pragma unroll
            for (int j = 0; j < 5; j++) {
                ffma2(a0, wA[i * 5 + j], pr[j]);
                ffma2(a1, wB[i * 5 + j], pr[j + 1]);
            }
        }
        float2 aP0 = make_float2(aP0e.x + aP0o.x, aP0e.y + aP0o.y);
        float2 aP1 = make_float2(aP1e.x + aP1o.x, aP1e.y + aP1o.y);
        *(float4*)ob = make_float4(aP0.x, aP0.y, aP1.x, aP1.y);
        ob += (size_t)HHI * WHI;
        xr = xn;
#pragma unroll
        for (int i = 0; i < 15; i++) cur[i] = nxt[i];
    }
}

// ------------------------- launch -------------------------
extern "C" void kernel_launch(void* const* d_in, const int* in_sizes, int n_in,
                              void* d_out, int out_size) {
    const float* X      = (const float*)d_in[0];
    const float* comp_w = (const float*)d_in[1];
    const float* comp_b = (const float*)d_in[2];
    const float* bn1_g  = (const float*)d_in[3];
    const float* bn1_b  = (const float*)d_in[4];
    const float* bn1_m  = (const float*)d_in[5];
    const float* bn1_v  = (const float*)d_in[6];
    const float* enc_w  = (const float*)d_in[7];
    const float* enc_b  = (const float*)d_in[8];
    const float* bn2_g  = (const float*)d_in[9];
    const float* bn2_b  = (const float*)d_in[10];
    const float* bn2_m  = (const float*)d_in[11];
    const float* bn2_v  = (const float*)d_in[12];
    float* out = (float*)d_out;

    k0_prep<<<252, 256>>>(comp_w, comp_b, bn1_g, bn1_b, bn1_m, bn1_v,
                          enc_w, enc_b, bn2_g, bn2_b, bn2_m, bn2_v);
    k1_conv1<<<dim3(32, 8), 256>>>(X);
    k_bilinear<<<18496, 256>>>(X);
    k2_tensor<<<dim3(32, 8), 256>>>();
    k3_reassemble<<<dim3(32, 8, 8), 128>>>(out);
}